// round 14
// baseline (speedup 1.0000x reference)
#include <cuda_runtime.h>

// ElevationLoss: tversky(logits, gt) * elevation(softmax, heights, gt)
// B=8, C=2, H=W=512, gt in {0,1}. Strip kernel: block = 8 rows x 256 cols.
// Thread = 1 col x 8 rows, rolling 3x3 register window over smem rows.
// Smem cell (A,B) = (2g-1, -A*h); enc = 1 + A/16 packs (count, sumA) per test.
// R14: __launch_bounds__(NT, 6) to force >=6 blocks/SM (occupancy experiment).

#define IMG_W 512
#define IMG_H 512
#define HW (IMG_H * IMG_W)        // 262144
#define NBATCH 8
#define NPIX (NBATCH * HW)        // 2097152
#define NT 256
#define NBLK 1024                 // 8 images x 64 strips x 2 col-halves
#define SW2 260                   // padded smem row width (cells)
#define NACC 5

// SoA per-block partials: [Σp1, inter1, count1, comb_sum, ud_sum]
__device__ float g_part5[NACC][NBLK];
__device__ unsigned g_count = 0;               // reset by last block each launch
__device__ __align__(16) float g_zrowf[IMG_W]; // zero-initialized, never written
__device__ __align__(16) int   g_zrowi[IMG_W]; // zero-initialized, never written

__device__ __forceinline__ float block_reduce(float v, float* sh) {
    #pragma unroll
    for (int o = 16; o > 0; o >>= 1) v += __shfl_down_sync(0xffffffffu, v, o);
    int lane = threadIdx.x & 31;
    int w = threadIdx.x >> 5;
    __syncthreads();                 // protect sh reuse across calls
    if (lane == 0) sh[w] = v;
    __syncthreads();
    if (w == 0) {
        v = (lane < NT / 32) ? sh[lane] : 0.0f;
        #pragma unroll
        for (int o = 4; o > 0; o >>= 1) v += __shfl_down_sync(0xffffffffu, v, o);
    }
    return v;   // valid in thread 0
}

__global__ __launch_bounds__(NT, 6) void elev_fused(
    const float* __restrict__ pred,   // (B,2,H,W)
    const float* __restrict__ hgt,    // (B,1,H,W)
    const int*   __restrict__ gt,     // (B,1,H,W)
    float* __restrict__ out)
{
    __shared__ float2 sm[10 * SW2];  // rows y0-1 .. y0+8, cols x0-1 .. x0+256
    __shared__ float  shred[NT / 32];

    int tid = threadIdx.x;
    int bi  = blockIdx.x;
    int b     = bi >> 7;             // image
    int rr    = bi & 127;
    int strip = rr >> 1;             // 64 strips of 8 rows
    int half  = rr & 1;              // 2 col-halves of 256
    int y0    = strip << 3;
    int x0    = half << 8;

    const float* pb = pred + ((size_t)b * 2) * HW;
    const float* hb = hgt + (size_t)b * HW;
    const int*   gb = gt  + (size_t)b * HW;

    // ---- logit prefetch: t[p] = l1 - l0 for the thread's column ----
    float t[8];
    {
        const float* lp = pb + (y0 << 9) + x0 + tid;
        #pragma unroll
        for (int p = 0; p < 8; p++)
            t[p] = lp[HW + (p << 9)] - lp[p << 9];
    }

    // ---- smem fill: 10 rows x 64 vec4 chunks = 640 tasks ----
    #pragma unroll
    for (int i = 0; i < 3; i++) {
        int task = tid + (i << 8);
        if (task < 640) {
            int k = task >> 6;       // smem row 0..9
            int j = task & 63;       // vec4 chunk (4 cols)
            int y = y0 - 1 + k;
            bool v = (unsigned)y < (unsigned)IMG_H;
            const int*   gp = v ? (gb + (y << 9) + x0) : (g_zrowi + x0);
            const float* hp = v ? (hb + (y << 9) + x0) : (g_zrowf + x0);
            int4   g4 = ((const int4*)  gp)[j];
            float4 h4 = ((const float4*)hp)[j];
            float A0 = (float)(2 * g4.x - 1), A1 = (float)(2 * g4.y - 1);
            float A2 = (float)(2 * g4.z - 1), A3 = (float)(2 * g4.w - 1);
            float4* dst = (float4*)&sm[k * SW2 + 2 + (j << 2)];
            dst[0] = make_float4(A0, -A0 * h4.x, A1, -A1 * h4.y);
            dst[1] = make_float4(A2, -A2 * h4.z, A3, -A3 * h4.w);
        }
    }
    if (tid < 20) {                  // halo cols (x0-1 at sc=1, x0+256 at sc=258)
        int k    = tid >> 1;
        int side = tid & 1;
        int xcol = side ? (x0 + 256) : (x0 - 1);
        int sc   = side ? 258 : 1;
        int y    = y0 - 1 + k;
        bool vy = (unsigned)y < (unsigned)IMG_H;
        bool vx = (unsigned)xcol < (unsigned)IMG_W;
        const int*   gp = vy ? (gb + (y << 9)) : g_zrowi;
        const float* hp = vy ? (hb + (y << 9)) : g_zrowf;
        int   g = vx ? gp[xcol] : 0;
        float h = vx ? hp[xcol] : 0.f;
        float A = (float)(2 * g - 1);
        sm[k * SW2 + sc] = make_float2(A, -A * h);
    }
    __syncthreads();

    // ---- compute: 8 pixels down the column, rolling 3x3 window ----
    float s_p1 = 0.f, s_i1 = 0.f, s_cb8 = 0.f, s_udr = 0.f, s_uac = 0.f;
    int c1i = 0;

    const float2* col = sm + tid + 1;    // cells at +0,+1,+2 = left,center,right
    float2 X0[3], X1[3];
    float  e0[3], e1[3];
    #pragma unroll
    for (int j = 0; j < 3; j++) {
        X0[j] = col[j];                  // smem row 0
        X1[j] = col[SW2 + j];            // smem row 1
        e0[j] = fmaf(0.0625f, X0[j].x, 1.0f);
        e1[j] = fmaf(0.0625f, X1[j].x, 1.0f);
    }

    #pragma unroll
    for (int p = 0; p < 8; p++) {
        float2 N[3];
        float  e2[3];
        #pragma unroll
        for (int j = 0; j < 3; j++) {
            N[j]  = col[(p + 2) * SW2 + j];
            e2[j] = fmaf(0.0625f, N[j].x, 1.0f);
        }

        float Ac = X1[1].x;
        float hc = -Ac * X1[1].y;        // exact: B = -A*h, A = ±1

        // 8 neighbor tests (self excluded): pass iff A*hc + B <= 0.
        // Pass adds enc = 1 + A/16 into acc (sign-bit mask, branchless).
        float acc = 0.f;
        #pragma unroll
        for (int j = 0; j < 3; j++) {
            float m0 = fmaf(X0[j].x, hc, X0[j].y);
            acc += __int_as_float((__float_as_int(m0) >> 31) & __float_as_int(e0[j]));
            float m2 = fmaf(N[j].x, hc, N[j].y);
            acc += __int_as_float((__float_as_int(m2) >> 31) & __float_as_int(e2[j]));
        }
        {
            float ml = fmaf(X1[0].x, hc, X1[0].y);
            acc += __int_as_float((__float_as_int(ml) >> 31) & __float_as_int(e1[0]));
            float mr = fmaf(X1[2].x, hc, X1[2].y);
            acc += __int_as_float((__float_as_int(mr) >> 31) & __float_as_int(e1[2]));
        }

        // softmax + unified pred + tversky partials
        float p1 = 1.0f / (1.0f + __expf(-t[p]));
        s_p1 += p1;
        if (Ac > 0.f) { s_i1 += p1; c1i++; }
        float u = (t[p] > 0.f) ? p1 : p1 - 1.f;

        // decode packed acc: cb8 = rintf(acc), sumA/16 = acc - cb8
        float cbf = rintf(acc);
        s_cb8 += cbf;
        s_udr = fmaf(u, acc - cbf, s_udr);
        s_uac = fmaf(u, Ac, s_uac);

        // rotate window
        #pragma unroll
        for (int j = 0; j < 3; j++) {
            X0[j] = X1[j]; e0[j] = e1[j];
            X1[j] = N[j];  e1[j] = e2[j];
        }
    }

    // ---- per-block reduction (SoA partials) ----
    // csum: +1 per pixel for self (8/thread). uds = -16*s_udr - s_uac
    // (pass adds -A to dd; self adds -Ac).
    {
        float acc5[NACC] = {s_p1, s_i1, (float)c1i,
                            s_cb8 + 8.0f, -16.0f * s_udr - s_uac};
        #pragma unroll
        for (int k = 0; k < NACC; k++) {
            float r = block_reduce(acc5[k], shred);
            if (threadIdx.x == 0) g_part5[k][bi] = r;
        }
    }

    // ---- last-block finalize ----
    __shared__ bool is_last;
    if (tid == 0) {
        __threadfence();                     // publish this block's partials
        unsigned c = atomicAdd(&g_count, 1u);
        is_last = (c == (unsigned)(NBLK - 1));
    }
    __syncthreads();
    if (!is_last) return;
    __threadfence();                         // acquire all blocks' partials

    float acc[NACC];
    #pragma unroll
    for (int k = 0; k < NACC; k++) {
        float a = 0.0f;
        for (int i = tid; i < NBLK; i += NT)
            a += g_part5[k][i];              // coalesced
        acc[k] = a;
    }
    float tot[NACC];
    #pragma unroll
    for (int k = 0; k < NACC; k++) tot[k] = block_reduce(acc[k], shred);

    if (tid == 0) {
        const float ALPHA = 0.3f, BETA = 0.7f, GAMMA = 1.33f, EPS = 1e-7f;
        float p1s  = tot[0];
        float i1   = tot[1];
        float c1   = tot[2];
        float csum = tot[3];
        float uds  = tot[4];

        float p0s = (float)NPIX - p1s;
        float c0f = (float)NPIX - c1;
        float i0  = (float)NPIX - c1 - p1s + i1;   // sum((1-cf)*(1-p1))

        float fp0 = p0s - i0;
        float fn0 = c0f - i0;
        float d0  = fmaxf(i0 + ALPHA * fp0 + BETA * fn0 + EPS, EPS);
        float loss0 = powf(1.0f - i0 / d0, GAMMA) * (c0f > 0.0f ? 1.0f : 0.0f);

        float fp1 = p1s - i1;
        float fn1 = c1 - i1;
        float d1  = fmaxf(i1 + ALPHA * fp1 + BETA * fn1 + EPS, EPS);
        float loss1 = powf(1.0f - i1 / d1, GAMMA) * (c1 > 0.0f ? 1.0f : 0.0f);

        float tversky = 0.5f * (loss0 + loss1);
        float elev    = (csum + uds) / fmaxf(csum, 1.0f);

        out[0] = tversky * elev;
        g_count = 0;   // reset for next graph replay
    }
}

extern "C" void kernel_launch(void* const* d_in, const int* in_sizes, int n_in,
                              void* d_out, int out_size)
{
    const float* pred = (const float*)d_in[0];   // (8,2,512,512) f32
    const float* hgt  = (const float*)d_in[1];   // (8,1,512,512) f32
    const int*   gt   = (const int*)  d_in[2];   // (8,1,512,512) i32
    float* out = (float*)d_out;

    elev_fused<<<NBLK, NT>>>(pred, hgt, gt, out);
}

// round 15
// speedup vs baseline: 1.1850x; 1.1850x over previous
#include <cuda_runtime.h>

// ElevationLoss: tversky(logits, gt) * elevation(softmax, heights, gt)
// B=8, C=2, H=W=512, gt in {0,1}. Strip kernel: block = 8 rows x 256 cols.
// Thread = 1 col x 8 rows, rolling 3x3 register window over smem rows.
// Smem cell (A,B) = (2g-1, -A*h); enc = 1 + A/16 packs (count, sumA) per test.
// R15: sigmoid via single MUFU tanh.approx (was EX2+RCP = 2 MUFU) — the MUFU
// pipe (2 ops/px, rt=8/SMSP) models to ~24-28us: exactly the observed floor.

#define IMG_W 512
#define IMG_H 512
#define HW (IMG_H * IMG_W)        // 262144
#define NBATCH 8
#define NPIX (NBATCH * HW)        // 2097152
#define NT 256
#define NBLK 1024                 // 8 images x 64 strips x 2 col-halves
#define SW2 260                   // padded smem row width (cells)
#define NACC 5

// SoA per-block partials: [Σp1, inter1, count1, comb_sum, ud_sum]
__device__ float g_part5[NACC][NBLK];
__device__ unsigned g_count = 0;               // reset by last block each launch
__device__ __align__(16) float g_zrowf[IMG_W]; // zero-initialized, never written
__device__ __align__(16) int   g_zrowi[IMG_W]; // zero-initialized, never written

__device__ __forceinline__ float block_reduce(float v, float* sh) {
    #pragma unroll
    for (int o = 16; o > 0; o >>= 1) v += __shfl_down_sync(0xffffffffu, v, o);
    int lane = threadIdx.x & 31;
    int w = threadIdx.x >> 5;
    __syncthreads();                 // protect sh reuse across calls
    if (lane == 0) sh[w] = v;
    __syncthreads();
    if (w == 0) {
        v = (lane < NT / 32) ? sh[lane] : 0.0f;
        #pragma unroll
        for (int o = 4; o > 0; o >>= 1) v += __shfl_down_sync(0xffffffffu, v, o);
    }
    return v;   // valid in thread 0
}

__global__ __launch_bounds__(NT) void elev_fused(
    const float* __restrict__ pred,   // (B,2,H,W)
    const float* __restrict__ hgt,    // (B,1,H,W)
    const int*   __restrict__ gt,     // (B,1,H,W)
    float* __restrict__ out)
{
    __shared__ float2 sm[10 * SW2];  // rows y0-1 .. y0+8, cols x0-1 .. x0+256
    __shared__ float  shred[NT / 32];

    int tid = threadIdx.x;
    int bi  = blockIdx.x;
    int b     = bi >> 7;             // image
    int rr    = bi & 127;
    int strip = rr >> 1;             // 64 strips of 8 rows
    int half  = rr & 1;              // 2 col-halves of 256
    int y0    = strip << 3;
    int x0    = half << 8;

    const float* pb = pred + ((size_t)b * 2) * HW;
    const float* hb = hgt + (size_t)b * HW;
    const int*   gb = gt  + (size_t)b * HW;

    // ---- logit prefetch: t[p] = l1 - l0 for the thread's column ----
    float t[8];
    {
        const float* lp = pb + (y0 << 9) + x0 + tid;
        #pragma unroll
        for (int p = 0; p < 8; p++)
            t[p] = lp[HW + (p << 9)] - lp[p << 9];
    }

    // ---- smem fill: 10 rows x 64 vec4 chunks = 640 tasks ----
    #pragma unroll
    for (int i = 0; i < 3; i++) {
        int task = tid + (i << 8);
        if (task < 640) {
            int k = task >> 6;       // smem row 0..9
            int j = task & 63;       // vec4 chunk (4 cols)
            int y = y0 - 1 + k;
            bool v = (unsigned)y < (unsigned)IMG_H;
            const int*   gp = v ? (gb + (y << 9) + x0) : (g_zrowi + x0);
            const float* hp = v ? (hb + (y << 9) + x0) : (g_zrowf + x0);
            int4   g4 = ((const int4*)  gp)[j];
            float4 h4 = ((const float4*)hp)[j];
            float A0 = (float)(2 * g4.x - 1), A1 = (float)(2 * g4.y - 1);
            float A2 = (float)(2 * g4.z - 1), A3 = (float)(2 * g4.w - 1);
            float4* dst = (float4*)&sm[k * SW2 + 2 + (j << 2)];
            dst[0] = make_float4(A0, -A0 * h4.x, A1, -A1 * h4.y);
            dst[1] = make_float4(A2, -A2 * h4.z, A3, -A3 * h4.w);
        }
    }
    if (tid < 20) {                  // halo cols (x0-1 at sc=1, x0+256 at sc=258)
        int k    = tid >> 1;
        int side = tid & 1;
        int xcol = side ? (x0 + 256) : (x0 - 1);
        int sc   = side ? 258 : 1;
        int y    = y0 - 1 + k;
        bool vy = (unsigned)y < (unsigned)IMG_H;
        bool vx = (unsigned)xcol < (unsigned)IMG_W;
        const int*   gp = vy ? (gb + (y << 9)) : g_zrowi;
        const float* hp = vy ? (hb + (y << 9)) : g_zrowf;
        int   g = vx ? gp[xcol] : 0;
        float h = vx ? hp[xcol] : 0.f;
        float A = (float)(2 * g - 1);
        sm[k * SW2 + sc] = make_float2(A, -A * h);
    }
    __syncthreads();

    // ---- compute: 8 pixels down the column, rolling 3x3 window ----
    float s_p1 = 0.f, s_i1 = 0.f, s_cb8 = 0.f, s_udr = 0.f, s_uac = 0.f;
    int c1i = 0;

    const float2* col = sm + tid + 1;    // cells at +0,+1,+2 = left,center,right
    float2 X0[3], X1[3];
    float  e0[3], e1[3];
    #pragma unroll
    for (int j = 0; j < 3; j++) {
        X0[j] = col[j];                  // smem row 0
        X1[j] = col[SW2 + j];            // smem row 1
        e0[j] = fmaf(0.0625f, X0[j].x, 1.0f);
        e1[j] = fmaf(0.0625f, X1[j].x, 1.0f);
    }

    #pragma unroll
    for (int p = 0; p < 8; p++) {
        float2 N[3];
        float  e2[3];
        #pragma unroll
        for (int j = 0; j < 3; j++) {
            N[j]  = col[(p + 2) * SW2 + j];
            e2[j] = fmaf(0.0625f, N[j].x, 1.0f);
        }

        float Ac = X1[1].x;
        float hc = -Ac * X1[1].y;        // exact: B = -A*h, A = ±1

        // 8 neighbor tests (self excluded): pass iff A*hc + B <= 0.
        // Pass adds enc = 1 + A/16 into acc (sign-bit mask, branchless).
        float acc = 0.f;
        #pragma unroll
        for (int j = 0; j < 3; j++) {
            float m0 = fmaf(X0[j].x, hc, X0[j].y);
            acc += __int_as_float((__float_as_int(m0) >> 31) & __float_as_int(e0[j]));
            float m2 = fmaf(N[j].x, hc, N[j].y);
            acc += __int_as_float((__float_as_int(m2) >> 31) & __float_as_int(e2[j]));
        }
        {
            float ml = fmaf(X1[0].x, hc, X1[0].y);
            acc += __int_as_float((__float_as_int(ml) >> 31) & __float_as_int(e1[0]));
            float mr = fmaf(X1[2].x, hc, X1[2].y);
            acc += __int_as_float((__float_as_int(mr) >> 31) & __float_as_int(e1[2]));
        }

        // sigmoid via single MUFU: p1 = 0.5 + 0.5*tanh(t/2)
        float th;
        asm("tanh.approx.f32 %0, %1;" : "=f"(th) : "f"(0.5f * t[p]));
        float p1 = fmaf(0.5f, th, 0.5f);
        s_p1 += p1;
        if (Ac > 0.f) { s_i1 += p1; c1i++; }
        float u = (t[p] > 0.f) ? p1 : p1 - 1.f;

        // decode packed acc: cb8 = rintf(acc), sumA/16 = acc - cb8
        float cbf = rintf(acc);
        s_cb8 += cbf;
        s_udr = fmaf(u, acc - cbf, s_udr);
        s_uac = fmaf(u, Ac, s_uac);

        // rotate window
        #pragma unroll
        for (int j = 0; j < 3; j++) {
            X0[j] = X1[j]; e0[j] = e1[j];
            X1[j] = N[j];  e1[j] = e2[j];
        }
    }

    // ---- per-block reduction (SoA partials) ----
    // csum: +1 per pixel for self (8/thread). uds = -16*s_udr - s_uac
    // (pass adds -A to dd; self adds -Ac).
    {
        float acc5[NACC] = {s_p1, s_i1, (float)c1i,
                            s_cb8 + 8.0f, -16.0f * s_udr - s_uac};
        #pragma unroll
        for (int k = 0; k < NACC; k++) {
            float r = block_reduce(acc5[k], shred);
            if (threadIdx.x == 0) g_part5[k][bi] = r;
        }
    }

    // ---- last-block finalize ----
    __shared__ bool is_last;
    if (tid == 0) {
        __threadfence();                     // publish this block's partials
        unsigned c = atomicAdd(&g_count, 1u);
        is_last = (c == (unsigned)(NBLK - 1));
    }
    __syncthreads();
    if (!is_last) return;
    __threadfence();                         // acquire all blocks' partials

    float acc[NACC];
    #pragma unroll
    for (int k = 0; k < NACC; k++) {
        float a = 0.0f;
        for (int i = tid; i < NBLK; i += NT)
            a += g_part5[k][i];              // coalesced
        acc[k] = a;
    }
    float tot[NACC];
    #pragma unroll
    for (int k = 0; k < NACC; k++) tot[k] = block_reduce(acc[k], shred);

    if (tid == 0) {
        const float ALPHA = 0.3f, BETA = 0.7f, GAMMA = 1.33f, EPS = 1e-7f;
        float p1s  = tot[0];
        float i1   = tot[1];
        float c1   = tot[2];
        float csum = tot[3];
        float uds  = tot[4];

        float p0s = (float)NPIX - p1s;
        float c0f = (float)NPIX - c1;
        float i0  = (float)NPIX - c1 - p1s + i1;   // sum((1-cf)*(1-p1))

        float fp0 = p0s - i0;
        float fn0 = c0f - i0;
        float d0  = fmaxf(i0 + ALPHA * fp0 + BETA * fn0 + EPS, EPS);
        float loss0 = powf(1.0f - i0 / d0, GAMMA) * (c0f > 0.0f ? 1.0f : 0.0f);

        float fp1 = p1s - i1;
        float fn1 = c1 - i1;
        float d1  = fmaxf(i1 + ALPHA * fp1 + BETA * fn1 + EPS, EPS);
        float loss1 = powf(1.0f - i1 / d1, GAMMA) * (c1 > 0.0f ? 1.0f : 0.0f);

        float tversky = 0.5f * (loss0 + loss1);
        float elev    = (csum + uds) / fmaxf(csum, 1.0f);

        out[0] = tversky * elev;
        g_count = 0;   // reset for next graph replay
    }
}

extern "C" void kernel_launch(void* const* d_in, const int* in_sizes, int n_in,
                              void* d_out, int out_size)
{
    const float* pred = (const float*)d_in[0];   // (8,2,512,512) f32
    const float* hgt  = (const float*)d_in[1];   // (8,1,512,512) f32
    const int*   gt   = (const int*)  d_in[2];   // (8,1,512,512) i32
    float* out = (float*)d_out;

    elev_fused<<<NBLK, NT>>>(pred, hgt, gt, out);
}